// round 3
// baseline (speedup 1.0000x reference)
#include <cuda_runtime.h>
#include <math.h>

// ---------------------------------------------------------------------------
// Problem constants (fixed shapes for SVTRBlock_43087111914328)
// ---------------------------------------------------------------------------
#define B_    8
#define SEQ   1024
#define DIM   768
#define NHEAD 12
#define HD    64
#define TD    2304          // 3*DIM
#define HMLP  3072          // 4*DIM
#define ROWS  (B_*SEQ)      // 8192

// ---------------------------------------------------------------------------
// Scratch (device globals; no allocation allowed in kernel_launch)
// ---------------------------------------------------------------------------
__device__ float g_qkv[B_ * SEQ * TD];                       //  75.5 MB
__device__ float g_sc[(size_t)B_ * NHEAD * SEQ * SEQ];       // 402.7 MB
__device__ float g_attn[ROWS * DIM];                         //  25.2 MB
__device__ float g_x1[ROWS * DIM];                           //  25.2 MB
__device__ float g_y[ROWS * DIM];                            //  25.2 MB
__device__ float g_h[ROWS * HMLP];                           // 100.7 MB

// ---------------------------------------------------------------------------
// Templated tiled SGEMM with fused epilogues.
//   C[M x N] = op(A) * op(B)
//   A: M x K row-major (lda). BT=false: B is K x N row-major (ldb).
//   BT=true: B is N x K row-major (ldb) -> computes A * B^T (used for Q*K^T).
// Batched via blockIdx.z decomposed as (zb, zh), zh = z % nh.
// All global loads are float4 (strides/offsets are multiples of 4 by shape).
// ---------------------------------------------------------------------------
enum { EPI_NONE = 0, EPI_BIAS = 1, EPI_BIAS_GELU = 2, EPI_BIAS_RES = 3, EPI_SCALE = 4 };

template <int BM, int BN, int BK, int TM, int TN, bool BT, int EPI>
__global__ void __launch_bounds__((BM / TM) * (BN / TN))
gemm_k(const float* __restrict__ A, int lda, long sAb, long sAh,
       const float* __restrict__ Bp, int ldb, long sBb, long sBh,
       float* __restrict__ C, int ldc, long sCb, long sCh,
       const float* __restrict__ bias,
       const float* __restrict__ res, int ldres,
       int K, int nh, float scale)
{
    constexpr int NT = (BM / TM) * (BN / TN);
    const int tid = threadIdx.x;
    const int z  = blockIdx.z;
    const int zb = z / nh;
    const int zh = z - zb * nh;
    A  += (size_t)zb * sAb + (size_t)zh * sAh;
    Bp += (size_t)zb * sBb + (size_t)zh * sBh;
    C  += (size_t)zb * sCb + (size_t)zh * sCh;

    const int rowBase = blockIdx.y * BM;
    const int colBase = blockIdx.x * BN;

    __shared__ float As[BK][BM + 4];
    __shared__ float Bs[BK][BN + 4];

    const int tx = tid % (BN / TN);
    const int ty = tid / (BN / TN);

    float acc[TM][TN];
#pragma unroll
    for (int i = 0; i < TM; i++)
#pragma unroll
        for (int j = 0; j < TN; j++) acc[i][j] = 0.0f;

    for (int k0 = 0; k0 < K; k0 += BK) {
        // ---- A tile (BM x BK), float4 along K, transposed into As[k][m]
        {
            constexpr int V = BM * (BK / 4);         // float4 loads in tile
            for (int i = tid; i < V; i += NT) {
                int m = i / (BK / 4), c = i % (BK / 4);
                float4 v = *(const float4*)&A[(size_t)(rowBase + m) * lda + k0 + 4 * c];
                As[4 * c + 0][m] = v.x;
                As[4 * c + 1][m] = v.y;
                As[4 * c + 2][m] = v.z;
                As[4 * c + 3][m] = v.w;
            }
        }
        // ---- B tile
        if (BT) {
            constexpr int V = BN * (BK / 4);
            for (int i = tid; i < V; i += NT) {
                int j = i / (BK / 4), c = i % (BK / 4);
                float4 v = *(const float4*)&Bp[(size_t)(colBase + j) * ldb + k0 + 4 * c];
                Bs[4 * c + 0][j] = v.x;
                Bs[4 * c + 1][j] = v.y;
                Bs[4 * c + 2][j] = v.z;
                Bs[4 * c + 3][j] = v.w;
            }
        } else {
            constexpr int V = BK * (BN / 4);
            for (int i = tid; i < V; i += NT) {
                int kk = i / (BN / 4), c = i % (BN / 4);
                float4 v = *(const float4*)&Bp[(size_t)(k0 + kk) * ldb + colBase + 4 * c];
                *(float4*)&Bs[kk][4 * c] = v;    // (BN+4)-pad keeps 16B alignment
            }
        }
        __syncthreads();

#pragma unroll
        for (int kk = 0; kk < BK; kk++) {
            float a[TM], b[TN];
#pragma unroll
            for (int i = 0; i < TM; i += 4)
                *(float4*)&a[i] = *(const float4*)&As[kk][ty * TM + i];
#pragma unroll
            for (int j = 0; j < TN; j += 4)
                *(float4*)&b[j] = *(const float4*)&Bs[kk][tx * TN + j];
#pragma unroll
            for (int i = 0; i < TM; i++)
#pragma unroll
                for (int j = 0; j < TN; j++)
                    acc[i][j] = fmaf(a[i], b[j], acc[i][j]);
        }
        __syncthreads();
    }

    // ---- epilogue
#pragma unroll
    for (int i = 0; i < TM; i++) {
        const int r = rowBase + ty * TM + i;
#pragma unroll
        for (int j = 0; j < TN; j++) {
            const int c = colBase + tx * TN + j;
            float v = acc[i][j];
            if (EPI == EPI_SCALE) v *= scale;
            if (EPI == EPI_BIAS || EPI == EPI_BIAS_GELU || EPI == EPI_BIAS_RES)
                v += bias[c];
            if (EPI == EPI_BIAS_GELU)
                v = 0.5f * v * (1.0f + erff(v * 0.70710678118654752f));
            if (EPI == EPI_BIAS_RES)
                v += res[(size_t)r * ldres + c];
            C[(size_t)r * ldc + c] = v;
        }
    }
}

// ---------------------------------------------------------------------------
// Row softmax over 1024 columns (one block = one row, 256 threads, float4)
// ---------------------------------------------------------------------------
__global__ void softmax_1024(float* __restrict__ S)
{
    __shared__ float sm[33];
    const size_t row = blockIdx.x;
    float4* p = reinterpret_cast<float4*>(S + row * 1024);
    float4 v = p[threadIdx.x];

    float m = fmaxf(fmaxf(v.x, v.y), fmaxf(v.z, v.w));
#pragma unroll
    for (int o = 16; o; o >>= 1) m = fmaxf(m, __shfl_xor_sync(0xffffffffu, m, o));
    const int w = threadIdx.x >> 5, l = threadIdx.x & 31;
    if (l == 0) sm[w] = m;
    __syncthreads();
    if (threadIdx.x == 0) {
        float r = sm[0];
#pragma unroll
        for (int i = 1; i < 8; i++) r = fmaxf(r, sm[i]);
        sm[32] = r;
    }
    __syncthreads();
    m = sm[32];

    v.x = __expf(v.x - m); v.y = __expf(v.y - m);
    v.z = __expf(v.z - m); v.w = __expf(v.w - m);
    float s = v.x + v.y + v.z + v.w;
#pragma unroll
    for (int o = 16; o; o >>= 1) s += __shfl_xor_sync(0xffffffffu, s, o);
    __syncthreads();
    if (l == 0) sm[w] = s;
    __syncthreads();
    if (threadIdx.x == 0) {
        float r = 0.0f;
#pragma unroll
        for (int i = 0; i < 8; i++) r += sm[i];
        sm[32] = r;
    }
    __syncthreads();
    const float inv = 1.0f / sm[32];
    v.x *= inv; v.y *= inv; v.z *= inv; v.w *= inv;
    p[threadIdx.x] = v;
}

// ---------------------------------------------------------------------------
// LayerNorm over 768 columns (one block = one row, 256 threads x 3 elems)
// ---------------------------------------------------------------------------
__global__ void layernorm_768(const float* __restrict__ in, float* __restrict__ out,
                              const float* __restrict__ g, const float* __restrict__ bb)
{
    __shared__ float sm[33];
    const size_t row = blockIdx.x;
    const float* p = in + row * DIM;
    const int t = threadIdx.x;
    const float x0 = p[t], x1 = p[t + 256], x2 = p[t + 512];

    float s = x0 + x1 + x2;
#pragma unroll
    for (int o = 16; o; o >>= 1) s += __shfl_xor_sync(0xffffffffu, s, o);
    const int w = t >> 5, l = t & 31;
    if (l == 0) sm[w] = s;
    __syncthreads();
    if (t == 0) {
        float r = 0.0f;
#pragma unroll
        for (int i = 0; i < 8; i++) r += sm[i];
        sm[32] = r;
    }
    __syncthreads();
    const float mu = sm[32] * (1.0f / DIM);

    const float d0 = x0 - mu, d1 = x1 - mu, d2 = x2 - mu;
    float q = d0 * d0 + d1 * d1 + d2 * d2;
#pragma unroll
    for (int o = 16; o; o >>= 1) q += __shfl_xor_sync(0xffffffffu, q, o);
    __syncthreads();
    if (l == 0) sm[w] = q;
    __syncthreads();
    if (t == 0) {
        float r = 0.0f;
#pragma unroll
        for (int i = 0; i < 8; i++) r += sm[i];
        sm[32] = r;
    }
    __syncthreads();
    const float var = sm[32] * (1.0f / DIM);
    const float inv = rsqrtf(var + 1e-6f);

    float* o = out + row * DIM;
    o[t]       = d0 * inv * g[t]       + bb[t];
    o[t + 256] = d1 * inv * g[t + 256] + bb[t + 256];
    o[t + 512] = d2 * inv * g[t + 512] + bb[t + 512];
}

// ---------------------------------------------------------------------------
// Launch
// ---------------------------------------------------------------------------
extern "C" void kernel_launch(void* const* d_in, const int* in_sizes, int n_in,
                              void* d_out, int out_size)
{
    const float* x      = (const float*)d_in[0];
    const float* qkv_w  = (const float*)d_in[1];
    const float* qkv_b  = (const float*)d_in[2];
    const float* proj_w = (const float*)d_in[3];
    const float* proj_b = (const float*)d_in[4];
    const float* ln1_g  = (const float*)d_in[5];
    const float* ln1_b  = (const float*)d_in[6];
    const float* ln2_g  = (const float*)d_in[7];
    const float* ln2_b  = (const float*)d_in[8];
    const float* fc1_w  = (const float*)d_in[9];
    const float* fc1_b  = (const float*)d_in[10];
    const float* fc2_w  = (const float*)d_in[11];
    const float* fc2_b  = (const float*)d_in[12];
    float* out = (float*)d_out;

    float *qkv, *sc, *attn, *x1, *y, *h;
    cudaGetSymbolAddress((void**)&qkv,  g_qkv);
    cudaGetSymbolAddress((void**)&sc,   g_sc);
    cudaGetSymbolAddress((void**)&attn, g_attn);
    cudaGetSymbolAddress((void**)&x1,   g_x1);
    cudaGetSymbolAddress((void**)&y,    g_y);
    cudaGetSymbolAddress((void**)&h,    g_h);

    // 1) QKV projection: [8192,768] @ [768,2304] + b -> g_qkv
    gemm_k<128,128,16,8,8,false,EPI_BIAS><<<dim3(TD/128, ROWS/128, 1), 256>>>(
        x, DIM, 0, 0,
        qkv_w, TD, 0, 0,
        qkv, TD, 0, 0,
        qkv_b, nullptr, 0, DIM, 1, 1.0f);

    // 2) Scores: per (b,h)  S = (Q @ K^T) * hd^-0.5    (both K-major, NT)
    gemm_k<128,128,16,8,8,true,EPI_SCALE><<<dim3(SEQ/128, SEQ/128, B_*NHEAD), 256>>>(
        qkv,        TD, (long)SEQ*TD, HD,            // Q (offset 0)
        qkv + DIM,  TD, (long)SEQ*TD, HD,            // K (offset D)
        sc, SEQ, (long)NHEAD*SEQ*SEQ, (long)SEQ*SEQ,
        nullptr, nullptr, 0, HD, NHEAD, 0.125f);

    // 3) softmax over keys
    softmax_1024<<<B_*NHEAD*SEQ, 256>>>(sc);

    // 4) PV: per (b,h)  O = P @ V  -> written head-interleaved into g_attn [B,N,D]
    gemm_k<128,64,16,8,4,false,EPI_NONE><<<dim3(1, SEQ/128, B_*NHEAD), 256>>>(
        sc, SEQ, (long)NHEAD*SEQ*SEQ, (long)SEQ*SEQ,
        qkv + 2*DIM, TD, (long)SEQ*TD, HD,           // V (offset 2D)
        attn, DIM, (long)SEQ*DIM, HD,
        nullptr, nullptr, 0, SEQ, NHEAD, 1.0f);

    // 5) Proj + bias + residual(x) -> g_y
    gemm_k<128,128,16,8,8,false,EPI_BIAS_RES><<<dim3(DIM/128, ROWS/128, 1), 256>>>(
        attn, DIM, 0, 0,
        proj_w, DIM, 0, 0,
        y, DIM, 0, 0,
        proj_b, x, DIM, DIM, 1, 1.0f);

    // 6) LN1 -> g_x1
    layernorm_768<<<ROWS, 256>>>(y, x1, ln1_g, ln1_b);

    // 7) FC1 + bias + exact GELU -> g_h
    gemm_k<128,128,16,8,8,false,EPI_BIAS_GELU><<<dim3(HMLP/128, ROWS/128, 1), 256>>>(
        x1, DIM, 0, 0,
        fc1_w, HMLP, 0, 0,
        h, HMLP, 0, 0,
        fc1_b, nullptr, 0, DIM, 1, 1.0f);

    // 8) FC2 + bias + residual(x1) -> g_y
    gemm_k<128,128,16,8,8,false,EPI_BIAS_RES><<<dim3(DIM/128, ROWS/128, 1), 256>>>(
        h, HMLP, 0, 0,
        fc2_w, DIM, 0, 0,
        y, DIM, 0, 0,
        fc2_b, x1, DIM, HMLP, 1, 1.0f);

    // 9) LN2 -> out
    layernorm_768<<<ROWS, 256>>>(y, out, ln2_g, ln2_b);
}

// round 4
// speedup vs baseline: 3.1040x; 3.1040x over previous
#include <cuda_runtime.h>
#include <math.h>
#include <stdint.h>

// ---------------------------------------------------------------------------
// Problem constants (fixed shapes for SVTRBlock_43087111914328)
// ---------------------------------------------------------------------------
#define B_    8
#define SEQ   1024
#define DIM   768
#define NHEAD 12
#define HD    64
#define TD    2304          // 3*DIM
#define HMLP  3072          // 4*DIM
#define ROWS  (B_*SEQ)      // 8192

// ---------------------------------------------------------------------------
// Scratch (device globals; no allocation allowed in kernel_launch)
// ---------------------------------------------------------------------------
__device__ float g_qkv[B_ * SEQ * TD];                       //  75.5 MB
__device__ float g_sc[(size_t)B_ * NHEAD * SEQ * SEQ];       // 402.7 MB
__device__ float g_attn[ROWS * DIM];                         //  25.2 MB
__device__ float g_x1[ROWS * DIM];                           //  25.2 MB
__device__ float g_y[ROWS * DIM];                            //  25.2 MB
__device__ float g_h[ROWS * HMLP];                           // 100.7 MB

// ---------------------------------------------------------------------------
// Helpers
// ---------------------------------------------------------------------------
static __device__ __forceinline__ uint32_t smem_u32(const void* p) {
    return (uint32_t)__cvta_generic_to_shared(p);
}
static __device__ __forceinline__ uint32_t f2tf(float f) {
    uint32_t r;
    asm("cvt.rna.tf32.f32 %0, %1;" : "=r"(r) : "f"(f));
    return r;
}
static __device__ __forceinline__ void mma_tf32(float c[4],
                                                uint32_t a0, uint32_t a1, uint32_t a2, uint32_t a3,
                                                uint32_t b0, uint32_t b1) {
    asm volatile(
        "mma.sync.aligned.m16n8k8.row.col.f32.tf32.tf32.f32 "
        "{%0,%1,%2,%3}, {%4,%5,%6,%7}, {%8,%9}, {%0,%1,%2,%3};"
        : "+f"(c[0]), "+f"(c[1]), "+f"(c[2]), "+f"(c[3])
        : "r"(a0), "r"(a1), "r"(a2), "r"(a3), "r"(b0), "r"(b1));
}
#define CP_ASYNC16(dst, src) \
    asm volatile("cp.async.cg.shared.global [%0], [%1], 16;" :: "r"(dst), "l"(src))
#define CP_COMMIT()  asm volatile("cp.async.commit_group;")
#define CP_WAIT_1()  asm volatile("cp.async.wait_group 1;")
#define CP_WAIT_0()  asm volatile("cp.async.wait_group 0;")

// ---------------------------------------------------------------------------
// TF32 tensor-core GEMM with fused epilogues.
//   C[M x N] = op(A) * op(B)
//   A: M x K row-major (lda).
//   BT=false: B is K x N row-major (ldb). BT=true: B is N x K row-major -> A*B^T.
// Block tile BM x BN, BK=16, 8 warps (WARPS_M x WARPS_N), warp tile 64x(BN/4).
// Batched via blockIdx.z decomposed as (zb, zh), zh = z % nh.
// All shapes divide tiles exactly (asserted by launch configs) -> no bounds checks.
// ---------------------------------------------------------------------------
enum { EPI_NONE = 0, EPI_BIAS = 1, EPI_BIAS_GELU = 2, EPI_BIAS_RES = 3, EPI_SCALE = 4 };

template <int BM, int BN, int WARPS_M, int WARPS_N, bool BT, int EPI>
__global__ void __launch_bounds__(256)
mma_gemm(const float* __restrict__ A, int lda, long sAb, long sAh,
         const float* __restrict__ Bp, int ldb, long sBb, long sBh,
         float* __restrict__ C, int ldc, long sCb, long sCh,
         const float* __restrict__ bias,
         const float* __restrict__ res, int ldres,
         int K, int nh, float scale)
{
    static_assert(WARPS_M * WARPS_N == 8, "256 threads");
    constexpr int BK  = 16;
    constexpr int WM  = BM / WARPS_M;     // rows per warp
    constexpr int WN  = BN / WARPS_N;     // cols per warp
    constexpr int MT  = WM / 16;          // m16 tiles per warp
    constexpr int NT_ = WN / 8;           // n8 tiles per warp
    constexpr int APAD = 20;              // [row][k] stride (conflict-free frag reads)
    constexpr int B_ROWS   = BT ? BN : BK;
    constexpr int B_STRIDE = BT ? APAD : (BN + 4);

    __shared__ float As[2][BM][APAD];
    __shared__ float Bs[2][B_ROWS][B_STRIDE];

    const int tid  = threadIdx.x;
    const int warp = tid >> 5;
    const int lane = tid & 31;
    const int gid  = lane >> 2;           // 0..7
    const int tig  = lane & 3;            // 0..3
    const int wm   = (warp / WARPS_N) * WM;
    const int wn   = (warp % WARPS_N) * WN;

    const int z  = blockIdx.z;
    const int zb = z / nh;
    const int zh = z - zb * nh;
    A  += (size_t)zb * sAb + (size_t)zh * sAh;
    Bp += (size_t)zb * sBb + (size_t)zh * sBh;
    C  += (size_t)zb * sCb + (size_t)zh * sCh;

    const int rowBase = blockIdx.y * BM;
    const int colBase = blockIdx.x * BN;

    float acc[MT][NT_][4];
#pragma unroll
    for (int i = 0; i < MT; i++)
#pragma unroll
        for (int j = 0; j < NT_; j++)
#pragma unroll
            for (int r = 0; r < 4; r++) acc[i][j][r] = 0.0f;

    auto load_tile = [&](int st, int k0) {
        // A tile: BM rows x 16 k  -> As[st][row][k], 4 float4 per row
        constexpr int AV = BM * 4;
#pragma unroll
        for (int i = tid; i < AV; i += 256) {
            int row = i >> 2, c = (i & 3) << 2;
            CP_ASYNC16(smem_u32(&As[st][row][c]),
                       &A[(size_t)(rowBase + row) * lda + k0 + c]);
        }
        if (BT) {
            // B tile (N-major): BN rows x 16 k -> Bs[st][n][k]
            constexpr int BV = BN * 4;
#pragma unroll
            for (int i = tid; i < BV; i += 256) {
                int row = i >> 2, c = (i & 3) << 2;
                CP_ASYNC16(smem_u32(&Bs[st][row][c]),
                           &Bp[(size_t)(colBase + row) * ldb + k0 + c]);
            }
        } else {
            // B tile (K-major): 16 rows x BN -> Bs[st][k][n]
            constexpr int BV = BK * (BN / 4);
#pragma unroll
            for (int i = tid; i < BV; i += 256) {
                int kk = i / (BN / 4), c = (i % (BN / 4)) << 2;
                CP_ASYNC16(smem_u32(&Bs[st][kk][c]),
                           &Bp[(size_t)(k0 + kk) * ldb + colBase + c]);
            }
        }
    };

    const int nTiles = K / BK;
    load_tile(0, 0);
    CP_COMMIT();

    for (int t = 0; t < nTiles; t++) {
        const int st = t & 1;
        if (t + 1 < nTiles) {
            load_tile((t + 1) & 1, (t + 1) * BK);
            CP_COMMIT();
            CP_WAIT_1();
        } else {
            CP_WAIT_0();
        }
        __syncthreads();

#pragma unroll
        for (int kb = 0; kb < BK; kb += 8) {
            uint32_t af[MT][4];
#pragma unroll
            for (int mt = 0; mt < MT; mt++) {
                const int m0 = wm + mt * 16;
                af[mt][0] = f2tf(As[st][m0 + gid    ][kb + tig    ]);
                af[mt][1] = f2tf(As[st][m0 + gid + 8][kb + tig    ]);
                af[mt][2] = f2tf(As[st][m0 + gid    ][kb + tig + 4]);
                af[mt][3] = f2tf(As[st][m0 + gid + 8][kb + tig + 4]);
            }
            uint32_t bf[NT_][2];
#pragma unroll
            for (int nt = 0; nt < NT_; nt++) {
                const int n0 = wn + nt * 8;
                if (BT) {
                    bf[nt][0] = f2tf(Bs[st][n0 + gid][kb + tig    ]);
                    bf[nt][1] = f2tf(Bs[st][n0 + gid][kb + tig + 4]);
                } else {
                    bf[nt][0] = f2tf(Bs[st][kb + tig    ][n0 + gid]);
                    bf[nt][1] = f2tf(Bs[st][kb + tig + 4][n0 + gid]);
                }
            }
#pragma unroll
            for (int mt = 0; mt < MT; mt++)
#pragma unroll
                for (int nt = 0; nt < NT_; nt++)
                    mma_tf32(acc[mt][nt], af[mt][0], af[mt][1], af[mt][2], af[mt][3],
                             bf[nt][0], bf[nt][1]);
        }
        __syncthreads();
    }

    // ---- epilogue: thread owns (row0,col),(row0,col+1),(row1,col),(row1,col+1)
#pragma unroll
    for (int mt = 0; mt < MT; mt++) {
        const int row0 = rowBase + wm + mt * 16 + gid;
        const int row1 = row0 + 8;
#pragma unroll
        for (int nt = 0; nt < NT_; nt++) {
            const int col = colBase + wn + nt * 8 + 2 * tig;
            float v0 = acc[mt][nt][0], v1 = acc[mt][nt][1];
            float v2 = acc[mt][nt][2], v3 = acc[mt][nt][3];
            if (EPI == EPI_SCALE) { v0 *= scale; v1 *= scale; v2 *= scale; v3 *= scale; }
            if (EPI == EPI_BIAS || EPI == EPI_BIAS_GELU || EPI == EPI_BIAS_RES) {
                const float b0 = bias[col], b1 = bias[col + 1];
                v0 += b0; v1 += b1; v2 += b0; v3 += b1;
            }
            if (EPI == EPI_BIAS_GELU) {
                v0 = 0.5f * v0 * (1.0f + erff(v0 * 0.70710678118654752f));
                v1 = 0.5f * v1 * (1.0f + erff(v1 * 0.70710678118654752f));
                v2 = 0.5f * v2 * (1.0f + erff(v2 * 0.70710678118654752f));
                v3 = 0.5f * v3 * (1.0f + erff(v3 * 0.70710678118654752f));
            }
            if (EPI == EPI_BIAS_RES) {
                const float2 r0 = *(const float2*)&res[(size_t)row0 * ldres + col];
                const float2 r1 = *(const float2*)&res[(size_t)row1 * ldres + col];
                v0 += r0.x; v1 += r0.y; v2 += r1.x; v3 += r1.y;
            }
            *(float2*)&C[(size_t)row0 * ldc + col] = make_float2(v0, v1);
            *(float2*)&C[(size_t)row1 * ldc + col] = make_float2(v2, v3);
        }
    }
}

// ---------------------------------------------------------------------------
// Row softmax over 1024 columns (one block = one row, 256 threads, float4)
// ---------------------------------------------------------------------------
__global__ void softmax_1024(float* __restrict__ S)
{
    __shared__ float sm[33];
    const size_t row = blockIdx.x;
    float4* p = reinterpret_cast<float4*>(S + row * 1024);
    float4 v = p[threadIdx.x];

    float m = fmaxf(fmaxf(v.x, v.y), fmaxf(v.z, v.w));
#pragma unroll
    for (int o = 16; o; o >>= 1) m = fmaxf(m, __shfl_xor_sync(0xffffffffu, m, o));
    const int w = threadIdx.x >> 5, l = threadIdx.x & 31;
    if (l == 0) sm[w] = m;
    __syncthreads();
    if (threadIdx.x == 0) {
        float r = sm[0];
#pragma unroll
        for (int i = 1; i < 8; i++) r = fmaxf(r, sm[i]);
        sm[32] = r;
    }
    __syncthreads();
    m = sm[32];

    v.x = __expf(v.x - m); v.y = __expf(v.y - m);
    v.z = __expf(v.z - m); v.w = __expf(v.w - m);
    float s = v.x + v.y + v.z + v.w;
#pragma unroll
    for (int o = 16; o; o >>= 1) s += __shfl_xor_sync(0xffffffffu, s, o);
    __syncthreads();
    if (l == 0) sm[w] = s;
    __syncthreads();
    if (threadIdx.x == 0) {
        float r = 0.0f;
#pragma unroll
        for (int i = 0; i < 8; i++) r += sm[i];
        sm[32] = r;
    }
    __syncthreads();
    const float inv = 1.0f / sm[32];
    v.x *= inv; v.y *= inv; v.z *= inv; v.w *= inv;
    p[threadIdx.x] = v;
}

// ---------------------------------------------------------------------------
// LayerNorm over 768 columns (one block = one row, 256 threads x 3 elems)
// ---------------------------------------------------------------------------
__global__ void layernorm_768(const float* __restrict__ in, float* __restrict__ out,
                              const float* __restrict__ g, const float* __restrict__ bb)
{
    __shared__ float sm[33];
    const size_t row = blockIdx.x;
    const float* p = in + row * DIM;
    const int t = threadIdx.x;
    const float x0 = p[t], x1 = p[t + 256], x2 = p[t + 512];

    float s = x0 + x1 + x2;
#pragma unroll
    for (int o = 16; o; o >>= 1) s += __shfl_xor_sync(0xffffffffu, s, o);
    const int w = t >> 5, l = t & 31;
    if (l == 0) sm[w] = s;
    __syncthreads();
    if (t == 0) {
        float r = 0.0f;
#pragma unroll
        for (int i = 0; i < 8; i++) r += sm[i];
        sm[32] = r;
    }
    __syncthreads();
    const float mu = sm[32] * (1.0f / DIM);

    const float d0 = x0 - mu, d1 = x1 - mu, d2 = x2 - mu;
    float q = d0 * d0 + d1 * d1 + d2 * d2;
#pragma unroll
    for (int o = 16; o; o >>= 1) q += __shfl_xor_sync(0xffffffffu, q, o);
    __syncthreads();
    if (l == 0) sm[w] = q;
    __syncthreads();
    if (t == 0) {
        float r = 0.0f;
#pragma unroll
        for (int i = 0; i < 8; i++) r += sm[i];
        sm[32] = r;
    }
    __syncthreads();
    const float var = sm[32] * (1.0f / DIM);
    const float inv = rsqrtf(var + 1e-6f);

    float* o = out + row * DIM;
    o[t]       = d0 * inv * g[t]       + bb[t];
    o[t + 256] = d1 * inv * g[t + 256] + bb[t + 256];
    o[t + 512] = d2 * inv * g[t + 512] + bb[t + 512];
}

// ---------------------------------------------------------------------------
// Launch
// ---------------------------------------------------------------------------
extern "C" void kernel_launch(void* const* d_in, const int* in_sizes, int n_in,
                              void* d_out, int out_size)
{
    const float* x      = (const float*)d_in[0];
    const float* qkv_w  = (const float*)d_in[1];
    const float* qkv_b  = (const float*)d_in[2];
    const float* proj_w = (const float*)d_in[3];
    const float* proj_b = (const float*)d_in[4];
    const float* ln1_g  = (const float*)d_in[5];
    const float* ln1_b  = (const float*)d_in[6];
    const float* ln2_g  = (const float*)d_in[7];
    const float* ln2_b  = (const float*)d_in[8];
    const float* fc1_w  = (const float*)d_in[9];
    const float* fc1_b  = (const float*)d_in[10];
    const float* fc2_w  = (const float*)d_in[11];
    const float* fc2_b  = (const float*)d_in[12];
    float* out = (float*)d_out;

    float *qkv, *sc, *attn, *x1, *y, *h;
    cudaGetSymbolAddress((void**)&qkv,  g_qkv);
    cudaGetSymbolAddress((void**)&sc,   g_sc);
    cudaGetSymbolAddress((void**)&attn, g_attn);
    cudaGetSymbolAddress((void**)&x1,   g_x1);
    cudaGetSymbolAddress((void**)&y,    g_y);
    cudaGetSymbolAddress((void**)&h,    g_h);

    // 1) QKV projection: [8192,768] @ [768,2304] + b -> g_qkv
    mma_gemm<128,128,2,4,false,EPI_BIAS><<<dim3(TD/128, ROWS/128, 1), 256>>>(
        x, DIM, 0, 0,
        qkv_w, TD, 0, 0,
        qkv, TD, 0, 0,
        qkv_b, nullptr, 0, DIM, 1, 1.0f);

    // 2) Scores: per (b,h)  S = (Q @ K^T) * hd^-0.5
    mma_gemm<128,128,2,4,true,EPI_SCALE><<<dim3(SEQ/128, SEQ/128, B_*NHEAD), 256>>>(
        qkv,        TD, (long)SEQ*TD, HD,            // Q (offset 0)
        qkv + DIM,  TD, (long)SEQ*TD, HD,            // K (offset D)
        sc, SEQ, (long)NHEAD*SEQ*SEQ, (long)SEQ*SEQ,
        nullptr, nullptr, 0, HD, NHEAD, 0.125f);

    // 3) softmax over keys
    softmax_1024<<<B_*NHEAD*SEQ, 256>>>(sc);

    // 4) PV: per (b,h)  O = P @ V  -> head-interleaved into g_attn [B,N,D]
    mma_gemm<128,64,2,4,false,EPI_NONE><<<dim3(1, SEQ/128, B_*NHEAD), 256>>>(
        sc, SEQ, (long)NHEAD*SEQ*SEQ, (long)SEQ*SEQ,
        qkv + 2*DIM, TD, (long)SEQ*TD, HD,           // V (offset 2D)
        attn, DIM, (long)SEQ*DIM, HD,
        nullptr, nullptr, 0, SEQ, NHEAD, 1.0f);

    // 5) Proj + bias + residual(x) -> g_y
    mma_gemm<128,128,2,4,false,EPI_BIAS_RES><<<dim3(DIM/128, ROWS/128, 1), 256>>>(
        attn, DIM, 0, 0,
        proj_w, DIM, 0, 0,
        y, DIM, 0, 0,
        proj_b, x, DIM, DIM, 1, 1.0f);

    // 6) LN1 -> g_x1
    layernorm_768<<<ROWS, 256>>>(y, x1, ln1_g, ln1_b);

    // 7) FC1 + bias + exact GELU -> g_h
    mma_gemm<128,128,2,4,false,EPI_BIAS_GELU><<<dim3(HMLP/128, ROWS/128, 1), 256>>>(
        x1, DIM, 0, 0,
        fc1_w, HMLP, 0, 0,
        h, HMLP, 0, 0,
        fc1_b, nullptr, 0, DIM, 1, 1.0f);

    // 8) FC2 + bias + residual(x1) -> g_y
    mma_gemm<128,128,2,4,false,EPI_BIAS_RES><<<dim3(DIM/128, ROWS/128, 1), 256>>>(
        h, HMLP, 0, 0,
        fc2_w, DIM, 0, 0,
        y, DIM, 0, 0,
        fc2_b, x1, DIM, HMLP, 1, 1.0f);

    // 9) LN2 -> out
    layernorm_768<<<ROWS, 256>>>(y, out, ln2_g, ln2_b);
}

// round 6
// speedup vs baseline: 3.5230x; 1.1350x over previous
#include <cuda_runtime.h>
#include <math.h>
#include <stdint.h>

// ---------------------------------------------------------------------------
// Problem constants (fixed shapes for SVTRBlock_43087111914328)
// ---------------------------------------------------------------------------
#define B_    8
#define SEQ   1024
#define DIM   768
#define NHEAD 12
#define HD    64
#define TD    2304          // 3*DIM
#define HMLP  3072          // 4*DIM
#define ROWS  (B_*SEQ)      // 8192

// ---------------------------------------------------------------------------
// Scratch (device globals; no allocation allowed in kernel_launch)
// ---------------------------------------------------------------------------
__device__ float g_qkv[B_ * SEQ * TD];                       //  75.5 MB
__device__ float g_attn[ROWS * DIM];                         //  25.2 MB
__device__ float g_x1[ROWS * DIM];                           //  25.2 MB
__device__ float g_y[ROWS * DIM];                            //  25.2 MB
__device__ float g_h[ROWS * HMLP];                           // 100.7 MB

// ---------------------------------------------------------------------------
// Helpers
// ---------------------------------------------------------------------------
static __device__ __forceinline__ uint32_t smem_u32(const void* p) {
    return (uint32_t)__cvta_generic_to_shared(p);
}
static __device__ __forceinline__ uint32_t f2tf(float f) {
    uint32_t r;
    asm("cvt.rna.tf32.f32 %0, %1;" : "=r"(r) : "f"(f));
    return r;
}
static __device__ __forceinline__ void mma_tf32(float c[4],
                                                uint32_t a0, uint32_t a1, uint32_t a2, uint32_t a3,
                                                uint32_t b0, uint32_t b1) {
    asm volatile(
        "mma.sync.aligned.m16n8k8.row.col.f32.tf32.tf32.f32 "
        "{%0,%1,%2,%3}, {%4,%5,%6,%7}, {%8,%9}, {%0,%1,%2,%3};"
        : "+f"(c[0]), "+f"(c[1]), "+f"(c[2]), "+f"(c[3])
        : "r"(a0), "r"(a1), "r"(a2), "r"(a3), "r"(b0), "r"(b1));
}
#define CP_ASYNC16(dst, src) \
    asm volatile("cp.async.cg.shared.global [%0], [%1], 16;" :: "r"(dst), "l"(src))
#define CP_COMMIT()  asm volatile("cp.async.commit_group;")
#define CP_WAIT_1()  asm volatile("cp.async.wait_group 1;")
#define CP_WAIT_0()  asm volatile("cp.async.wait_group 0;")

// ---------------------------------------------------------------------------
// TF32 tensor-core GEMM with fused epilogues (as validated in R4: 1600us).
// ---------------------------------------------------------------------------
enum { EPI_NONE = 0, EPI_BIAS = 1, EPI_BIAS_GELU = 2, EPI_BIAS_RES = 3, EPI_SCALE = 4 };

template <int BM, int BN, int WARPS_M, int WARPS_N, bool BT, int EPI>
__global__ void __launch_bounds__(256)
mma_gemm(const float* __restrict__ A, int lda, long sAb, long sAh,
         const float* __restrict__ Bp, int ldb, long sBb, long sBh,
         float* __restrict__ C, int ldc, long sCb, long sCh,
         const float* __restrict__ bias,
         const float* __restrict__ res, int ldres,
         int K, int nh, float scale)
{
    static_assert(WARPS_M * WARPS_N == 8, "256 threads");
    constexpr int BK  = 16;
    constexpr int WM  = BM / WARPS_M;
    constexpr int WN  = BN / WARPS_N;
    constexpr int MT  = WM / 16;
    constexpr int NT_ = WN / 8;
    constexpr int APAD = 20;
    constexpr int B_ROWS   = BT ? BN : BK;
    constexpr int B_STRIDE = BT ? APAD : (BN + 4);

    __shared__ float As[2][BM][APAD];
    __shared__ float Bs[2][B_ROWS][B_STRIDE];

    const int tid  = threadIdx.x;
    const int warp = tid >> 5;
    const int lane = tid & 31;
    const int gid  = lane >> 2;
    const int tig  = lane & 3;
    const int wm   = (warp / WARPS_N) * WM;
    const int wn   = (warp % WARPS_N) * WN;

    const int z  = blockIdx.z;
    const int zb = z / nh;
    const int zh = z - zb * nh;
    A  += (size_t)zb * sAb + (size_t)zh * sAh;
    Bp += (size_t)zb * sBb + (size_t)zh * sBh;
    C  += (size_t)zb * sCb + (size_t)zh * sCh;

    const int rowBase = blockIdx.y * BM;
    const int colBase = blockIdx.x * BN;

    float acc[MT][NT_][4];
#pragma unroll
    for (int i = 0; i < MT; i++)
#pragma unroll
        for (int j = 0; j < NT_; j++)
#pragma unroll
            for (int r = 0; r < 4; r++) acc[i][j][r] = 0.0f;

    auto load_tile = [&](int st, int k0) {
        constexpr int AV = BM * 4;
#pragma unroll
        for (int i = tid; i < AV; i += 256) {
            int row = i >> 2, c = (i & 3) << 2;
            CP_ASYNC16(smem_u32(&As[st][row][c]),
                       &A[(size_t)(rowBase + row) * lda + k0 + c]);
        }
        if (BT) {
            constexpr int BV = BN * 4;
#pragma unroll
            for (int i = tid; i < BV; i += 256) {
                int row = i >> 2, c = (i & 3) << 2;
                CP_ASYNC16(smem_u32(&Bs[st][row][c]),
                           &Bp[(size_t)(colBase + row) * ldb + k0 + c]);
            }
        } else {
            constexpr int BV = BK * (BN / 4);
#pragma unroll
            for (int i = tid; i < BV; i += 256) {
                int kk = i / (BN / 4), c = (i % (BN / 4)) << 2;
                CP_ASYNC16(smem_u32(&Bs[st][kk][c]),
                           &Bp[(size_t)(k0 + kk) * ldb + colBase + c]);
            }
        }
    };

    const int nTiles = K / BK;
    load_tile(0, 0);
    CP_COMMIT();

    for (int t = 0; t < nTiles; t++) {
        const int st = t & 1;
        if (t + 1 < nTiles) {
            load_tile((t + 1) & 1, (t + 1) * BK);
            CP_COMMIT();
            CP_WAIT_1();
        } else {
            CP_WAIT_0();
        }
        __syncthreads();

#pragma unroll
        for (int kb = 0; kb < BK; kb += 8) {
            uint32_t af[MT][4];
#pragma unroll
            for (int mt = 0; mt < MT; mt++) {
                const int m0 = wm + mt * 16;
                af[mt][0] = f2tf(As[st][m0 + gid    ][kb + tig    ]);
                af[mt][1] = f2tf(As[st][m0 + gid + 8][kb + tig    ]);
                af[mt][2] = f2tf(As[st][m0 + gid    ][kb + tig + 4]);
                af[mt][3] = f2tf(As[st][m0 + gid + 8][kb + tig + 4]);
            }
            uint32_t bf[NT_][2];
#pragma unroll
            for (int nt = 0; nt < NT_; nt++) {
                const int n0 = wn + nt * 8;
                if (BT) {
                    bf[nt][0] = f2tf(Bs[st][n0 + gid][kb + tig    ]);
                    bf[nt][1] = f2tf(Bs[st][n0 + gid][kb + tig + 4]);
                } else {
                    bf[nt][0] = f2tf(Bs[st][kb + tig    ][n0 + gid]);
                    bf[nt][1] = f2tf(Bs[st][kb + tig + 4][n0 + gid]);
                }
            }
#pragma unroll
            for (int mt = 0; mt < MT; mt++)
#pragma unroll
                for (int nt = 0; nt < NT_; nt++)
                    mma_tf32(acc[mt][nt], af[mt][0], af[mt][1], af[mt][2], af[mt][3],
                             bf[nt][0], bf[nt][1]);
        }
        __syncthreads();
    }

#pragma unroll
    for (int mt = 0; mt < MT; mt++) {
        const int row0 = rowBase + wm + mt * 16 + gid;
        const int row1 = row0 + 8;
#pragma unroll
        for (int nt = 0; nt < NT_; nt++) {
            const int col = colBase + wn + nt * 8 + 2 * tig;
            float v0 = acc[mt][nt][0], v1 = acc[mt][nt][1];
            float v2 = acc[mt][nt][2], v3 = acc[mt][nt][3];
            if (EPI == EPI_SCALE) { v0 *= scale; v1 *= scale; v2 *= scale; v3 *= scale; }
            if (EPI == EPI_BIAS || EPI == EPI_BIAS_GELU || EPI == EPI_BIAS_RES) {
                const float b0 = bias[col], b1 = bias[col + 1];
                v0 += b0; v1 += b1; v2 += b0; v3 += b1;
            }
            if (EPI == EPI_BIAS_GELU) {
                v0 = 0.5f * v0 * (1.0f + erff(v0 * 0.70710678118654752f));
                v1 = 0.5f * v1 * (1.0f + erff(v1 * 0.70710678118654752f));
                v2 = 0.5f * v2 * (1.0f + erff(v2 * 0.70710678118654752f));
                v3 = 0.5f * v3 * (1.0f + erff(v3 * 0.70710678118654752f));
            }
            if (EPI == EPI_BIAS_RES) {
                const float2 r0 = *(const float2*)&res[(size_t)row0 * ldres + col];
                const float2 r1 = *(const float2*)&res[(size_t)row1 * ldres + col];
                v0 += r0.x; v1 += r0.y; v2 += r1.x; v3 += r1.y;
            }
            *(float2*)&C[(size_t)row0 * ldc + col] = make_float2(v0, v1);
            *(float2*)&C[(size_t)row1 * ldc + col] = make_float2(v2, v3);
        }
    }
}

// ---------------------------------------------------------------------------
// Fused flash attention (TF32 mma, online softmax, S never leaves the SM).
// Grid: (8 q-tiles, 96 bh). 256 threads = 8 warps; warp w owns S rows 16w..16w+15.
// Smem: Qs[128][68] + double-buffered Ks/Vs[2][128][68]  (170 KB dynamic).
// P -> A-fragment conversion for PV done with width-4 shuffles (no smem P).
// ---------------------------------------------------------------------------
#define FA_PAD 68
#define FA_QOFF 0
#define FA_KOFF (128 * FA_PAD)
#define FA_VOFF (FA_KOFF + 2 * 128 * FA_PAD)
#define FA_SMEM ((FA_VOFF + 2 * 128 * FA_PAD) * 4)

__global__ void __launch_bounds__(256, 1)
flash_attn(const float* __restrict__ qkv, float* __restrict__ attn)
{
    extern __shared__ float sm[];
    float* Qs = sm + FA_QOFF;
    float* Ks = sm + FA_KOFF;   // [2][128][FA_PAD]
    float* Vs = sm + FA_VOFF;

    const int tid  = threadIdx.x;
    const int warp = tid >> 5;
    const int lane = tid & 31;
    const int gid  = lane >> 2;
    const int tig  = lane & 3;

    const int bh = blockIdx.y;
    const int b  = bh / NHEAD;
    const int h  = bh - b * NHEAD;
    const float* qp = qkv + (size_t)b * SEQ * TD + h * HD;
    const float* kp = qp + DIM;
    const float* vp = qp + 2 * DIM;
    const int q0 = blockIdx.x * 128;

    // ---- load Q tile + prefetch K0/V0 (one commit group)
#pragma unroll
    for (int i = tid; i < 128 * 16; i += 256) {
        int row = i >> 4, c = (i & 15) << 2;
        CP_ASYNC16(smem_u32(&Qs[row * FA_PAD + c]), &qp[(size_t)(q0 + row) * TD + c]);
    }
#pragma unroll
    for (int i = tid; i < 128 * 16; i += 256) {
        int row = i >> 4, c = (i & 15) << 2;
        CP_ASYNC16(smem_u32(&Ks[row * FA_PAD + c]), &kp[(size_t)row * TD + c]);
        CP_ASYNC16(smem_u32(&Vs[row * FA_PAD + c]), &vp[(size_t)row * TD + c]);
    }
    CP_COMMIT();

    uint32_t qf[8][4];                  // Q fragments, converted once
    float oacc[8][4];
#pragma unroll
    for (int i = 0; i < 8; i++)
#pragma unroll
        for (int r = 0; r < 4; r++) oacc[i][r] = 0.0f;
    float m0 = -1e30f, m1 = -1e30f, l0 = 0.0f, l1 = 0.0f;

    const int r0s = 16 * warp + gid;    // smem row (lo)
    for (int t = 0; t < 8; t++) {
        const int st = t & 1;
        if (t < 7) {
            const int nb = (t + 1) & 1;
            const float* kn = kp + (size_t)(t + 1) * 128 * TD;
            const float* vn = vp + (size_t)(t + 1) * 128 * TD;
#pragma unroll
            for (int i = tid; i < 128 * 16; i += 256) {
                int row = i >> 4, c = (i & 15) << 2;
                CP_ASYNC16(smem_u32(&Ks[(nb * 128 + row) * FA_PAD + c]), &kn[(size_t)row * TD + c]);
                CP_ASYNC16(smem_u32(&Vs[(nb * 128 + row) * FA_PAD + c]), &vn[(size_t)row * TD + c]);
            }
            CP_COMMIT();
            CP_WAIT_1();
        } else {
            CP_WAIT_0();
        }
        __syncthreads();

        if (t == 0) {
#pragma unroll
            for (int kb = 0; kb < 8; kb++) {
                qf[kb][0] = f2tf(Qs[(r0s    ) * FA_PAD + kb * 8 + tig    ]);
                qf[kb][1] = f2tf(Qs[(r0s + 8) * FA_PAD + kb * 8 + tig    ]);
                qf[kb][2] = f2tf(Qs[(r0s    ) * FA_PAD + kb * 8 + tig + 4]);
                qf[kb][3] = f2tf(Qs[(r0s + 8) * FA_PAD + kb * 8 + tig + 4]);
            }
        }

        // ---- S = Q @ K^T  (16 rows x 128 cols per warp)
        float sacc[16][4];
#pragma unroll
        for (int i = 0; i < 16; i++)
#pragma unroll
            for (int r = 0; r < 4; r++) sacc[i][r] = 0.0f;

        const float* Kb = Ks + st * 128 * FA_PAD;
#pragma unroll
        for (int kb = 0; kb < 8; kb++) {
#pragma unroll
            for (int nt = 0; nt < 16; nt++) {
                uint32_t b0 = f2tf(Kb[(nt * 8 + gid) * FA_PAD + kb * 8 + tig    ]);
                uint32_t b1 = f2tf(Kb[(nt * 8 + gid) * FA_PAD + kb * 8 + tig + 4]);
                mma_tf32(sacc[nt], qf[kb][0], qf[kb][1], qf[kb][2], qf[kb][3], b0, b1);
            }
        }

        // ---- online softmax (rows gid / gid+8; stats live within the quad)
        float mx0 = -1e30f, mx1 = -1e30f;
#pragma unroll
        for (int nt = 0; nt < 16; nt++) {
            sacc[nt][0] *= 0.125f; sacc[nt][1] *= 0.125f;
            sacc[nt][2] *= 0.125f; sacc[nt][3] *= 0.125f;
            mx0 = fmaxf(mx0, fmaxf(sacc[nt][0], sacc[nt][1]));
            mx1 = fmaxf(mx1, fmaxf(sacc[nt][2], sacc[nt][3]));
        }
        mx0 = fmaxf(mx0, __shfl_xor_sync(0xffffffffu, mx0, 1));
        mx0 = fmaxf(mx0, __shfl_xor_sync(0xffffffffu, mx0, 2));
        mx1 = fmaxf(mx1, __shfl_xor_sync(0xffffffffu, mx1, 1));
        mx1 = fmaxf(mx1, __shfl_xor_sync(0xffffffffu, mx1, 2));

        const float mn0 = fmaxf(m0, mx0), mn1 = fmaxf(m1, mx1);
        const float f0 = __expf(m0 - mn0), f1 = __expf(m1 - mn1);
        m0 = mn0; m1 = mn1;
        l0 *= f0;  l1 *= f1;
#pragma unroll
        for (int nd = 0; nd < 8; nd++) {
            oacc[nd][0] *= f0; oacc[nd][1] *= f0;
            oacc[nd][2] *= f1; oacc[nd][3] *= f1;
        }
#pragma unroll
        for (int nt = 0; nt < 16; nt++) {
            sacc[nt][0] = __expf(sacc[nt][0] - m0);
            sacc[nt][1] = __expf(sacc[nt][1] - m0);
            sacc[nt][2] = __expf(sacc[nt][2] - m1);
            sacc[nt][3] = __expf(sacc[nt][3] - m1);
            l0 += sacc[nt][0] + sacc[nt][1];
            l1 += sacc[nt][2] + sacc[nt][3];
        }

        // ---- O += P @ V   (A-frags built from sacc via width-4 shuffles)
        const float* Vb = Vs + st * 128 * FA_PAD;
        const int s1 = tig >> 1, s2 = s1 + 2;
        const bool odd = (tig & 1);
#pragma unroll
        for (int kk = 0; kk < 16; kk++) {
            float v00 = __shfl_sync(0xffffffffu, sacc[kk][0], s1, 4);
            float v01 = __shfl_sync(0xffffffffu, sacc[kk][1], s1, 4);
            float v02 = __shfl_sync(0xffffffffu, sacc[kk][0], s2, 4);
            float v03 = __shfl_sync(0xffffffffu, sacc[kk][1], s2, 4);
            float v10 = __shfl_sync(0xffffffffu, sacc[kk][2], s1, 4);
            float v11 = __shfl_sync(0xffffffffu, sacc[kk][3], s1, 4);
            float v12 = __shfl_sync(0xffffffffu, sacc[kk][2], s2, 4);
            float v13 = __shfl_sync(0xffffffffu, sacc[kk][3], s2, 4);
            uint32_t a0 = f2tf(odd ? v01 : v00);
            uint32_t a2 = f2tf(odd ? v03 : v02);
            uint32_t a1 = f2tf(odd ? v11 : v10);
            uint32_t a3 = f2tf(odd ? v13 : v12);
#pragma unroll
            for (int nd = 0; nd < 8; nd++) {
                uint32_t b0 = f2tf(Vb[(kk * 8 + tig    ) * FA_PAD + nd * 8 + gid]);
                uint32_t b1 = f2tf(Vb[(kk * 8 + tig + 4) * FA_PAD + nd * 8 + gid]);
                mma_tf32(oacc[nd], a0, a1, a2, a3, b0, b1);
            }
        }
        __syncthreads();
    }

    // ---- normalize and store (head-interleaved into attn [B,N,D])
    l0 += __shfl_xor_sync(0xffffffffu, l0, 1);
    l0 += __shfl_xor_sync(0xffffffffu, l0, 2);
    l1 += __shfl_xor_sync(0xffffffffu, l1, 1);
    l1 += __shfl_xor_sync(0xffffffffu, l1, 2);
    const float inv0 = 1.0f / l0, inv1 = 1.0f / l1;

    const size_t grow0 = (size_t)b * SEQ + q0 + 16 * warp + gid;
#pragma unroll
    for (int nd = 0; nd < 8; nd++) {
        const int col = h * HD + nd * 8 + 2 * tig;
        *(float2*)&attn[grow0 * DIM + col] =
            make_float2(oacc[nd][0] * inv0, oacc[nd][1] * inv0);
        *(float2*)&attn[(grow0 + 8) * DIM + col] =
            make_float2(oacc[nd][2] * inv1, oacc[nd][3] * inv1);
    }
}

// ---------------------------------------------------------------------------
// LayerNorm over 768 columns (one block = one row, 256 threads x 3 elems)
// ---------------------------------------------------------------------------
__global__ void layernorm_768(const float* __restrict__ in, float* __restrict__ out,
                              const float* __restrict__ g, const float* __restrict__ bb)
{
    __shared__ float sm[33];
    const size_t row = blockIdx.x;
    const float* p = in + row * DIM;
    const int t = threadIdx.x;
    const float x0 = p[t], x1 = p[t + 256], x2 = p[t + 512];

    float s = x0 + x1 + x2;
#pragma unroll
    for (int o = 16; o; o >>= 1) s += __shfl_xor_sync(0xffffffffu, s, o);
    const int w = t >> 5, l = t & 31;
    if (l == 0) sm[w] = s;
    __syncthreads();
    if (t == 0) {
        float r = 0.0f;
#pragma unroll
        for (int i = 0; i < 8; i++) r += sm[i];
        sm[32] = r;
    }
    __syncthreads();
    const float mu = sm[32] * (1.0f / DIM);

    const float d0 = x0 - mu, d1 = x1 - mu, d2 = x2 - mu;
    float q = d0 * d0 + d1 * d1 + d2 * d2;
#pragma unroll
    for (int o = 16; o; o >>= 1) q += __shfl_xor_sync(0xffffffffu, q, o);
    __syncthreads();
    if (l == 0) sm[w] = q;
    __syncthreads();
    if (t == 0) {
        float r = 0.0f;
#pragma unroll
        for (int i = 0; i < 8; i++) r += sm[i];
        sm[32] = r;
    }
    __syncthreads();
    const float var = sm[32] * (1.0f / DIM);
    const float inv = rsqrtf(var + 1e-6f);

    float* o = out + row * DIM;
    o[t]       = d0 * inv * g[t]       + bb[t];
    o[t + 256] = d1 * inv * g[t + 256] + bb[t + 256];
    o[t + 512] = d2 * inv * g[t + 512] + bb[t + 512];
}

// ---------------------------------------------------------------------------
// Launch
// ---------------------------------------------------------------------------
extern "C" void kernel_launch(void* const* d_in, const int* in_sizes, int n_in,
                              void* d_out, int out_size)
{
    const float* x      = (const float*)d_in[0];
    const float* qkv_w  = (const float*)d_in[1];
    const float* qkv_b  = (const float*)d_in[2];
    const float* proj_w = (const float*)d_in[3];
    const float* proj_b = (const float*)d_in[4];
    const float* ln1_g  = (const float*)d_in[5];
    const float* ln1_b  = (const float*)d_in[6];
    const float* ln2_g  = (const float*)d_in[7];
    const float* ln2_b  = (const float*)d_in[8];
    const float* fc1_w  = (const float*)d_in[9];
    const float* fc1_b  = (const float*)d_in[10];
    const float* fc2_w  = (const float*)d_in[11];
    const float* fc2_b  = (const float*)d_in[12];
    float* out = (float*)d_out;

    float *qkv, *attn, *x1, *y, *h;
    cudaGetSymbolAddress((void**)&qkv,  g_qkv);
    cudaGetSymbolAddress((void**)&attn, g_attn);
    cudaGetSymbolAddress((void**)&x1,   g_x1);
    cudaGetSymbolAddress((void**)&y,    g_y);
    cudaGetSymbolAddress((void**)&h,    g_h);

    // Unconditional (no static guards per harness rules); immediate host-side
    // attribute set, idempotent, not a stream operation -> capture-safe.
    cudaFuncSetAttribute(flash_attn, cudaFuncAttributeMaxDynamicSharedMemorySize, FA_SMEM);

    // 1) QKV projection: [8192,768] @ [768,2304] + b -> g_qkv
    mma_gemm<128,128,2,4,false,EPI_BIAS><<<dim3(TD/128, ROWS/128, 1), 256>>>(
        x, DIM, 0, 0,
        qkv_w, TD, 0, 0,
        qkv, TD, 0, 0,
        qkv_b, nullptr, 0, DIM, 1, 1.0f);

    // 2-4) Fused flash attention -> g_attn [B,N,D]
    flash_attn<<<dim3(SEQ/128, B_*NHEAD), 256, FA_SMEM>>>(qkv, attn);

    // 5) Proj + bias + residual(x) -> g_y
    mma_gemm<128,128,2,4,false,EPI_BIAS_RES><<<dim3(DIM/128, ROWS/128, 1), 256>>>(
        attn, DIM, 0, 0,
        proj_w, DIM, 0, 0,
        y, DIM, 0, 0,
        proj_b, x, DIM, DIM, 1, 1.0f);

    // 6) LN1 -> g_x1
    layernorm_768<<<ROWS, 256>>>(y, x1, ln1_g, ln1_b);

    // 7) FC1 + bias + exact GELU -> g_h
    mma_gemm<128,128,2,4,false,EPI_BIAS_GELU><<<dim3(HMLP/128, ROWS/128, 1), 256>>>(
        x1, DIM, 0, 0,
        fc1_w, HMLP, 0, 0,
        h, HMLP, 0, 0,
        fc1_b, nullptr, 0, DIM, 1, 1.0f);

    // 8) FC2 + bias + residual(x1) -> g_y
    mma_gemm<128,128,2,4,false,EPI_BIAS_RES><<<dim3(DIM/128, ROWS/128, 1), 256>>>(
        h, HMLP, 0, 0,
        fc2_w, DIM, 0, 0,
        y, DIM, 0, 0,
        fc2_b, x1, DIM, HMLP, 1, 1.0f);

    // 9) LN2 -> out
    layernorm_768<<<ROWS, 256>>>(y, out, ln2_g, ln2_b);
}